// round 15
// baseline (speedup 1.0000x reference)
#include <cuda_runtime.h>
#include <cuda_bf16.h>

// SE3Transform (PARTIAL_DENSE): for m in [0,M), i in [0,N):
//   nb = batch[i] + m*B;  out_pos[m*N+i] = R[nb] @ xyz[i] + p[nb];  out_batch[m*N+i] = nb
// Inputs: trans [M*B,4,4] f32, xyz [N,3] f32, batch [N] i32.
// Output: new_pos.ravel() [M*N*3] f32 ++ new_batch [M*N] as f32.
//
// R13 WIN: staged full-sector stores 21.3->18.2us. Strided/partial-sector
// global access was the binder.
// R14: mirror the fix on the load side — xyz read via 3 coalesced 512B
// LDG.128 per warp into the stage tile, then per-thread 48B reads from smem.
// Removes ~33 L1 wavefronts/warp of load inflation. Rest frozen.

#define BATCH_B 16
#define NMAT    128          // M*B
#define NPAIR   6            // float2 pairs per matrix (12 floats)
#define NSM     152          // GB300 SM count
#define THREADS 832
#define WARPS   (THREADS / 32)   // 26

__global__ void __launch_bounds__(THREADS, 1) se3_kernel(
        const float*  __restrict__ trans,
        const float4* __restrict__ xyz4,
        const float*  __restrict__ xyz,
        const int4*   __restrict__ batch4,
        const int*    __restrict__ batch,
        float* __restrict__ out,
        int N, int G, int M,
        long long posElems, int writeBatch)
{
    // float2-SoA transform table (conflict-free gathers).
    __shared__ float2 s2[NPAIR * NMAT];          // 6 KB
    // Per-warp staging tile: 96 float4 = 1536 B per warp (inputs, then outputs).
    __shared__ float4 sStage[WARPS * 96];        // 39.9 KB

    for (int idx = threadIdx.x; idx < NPAIR * NMAT; idx += blockDim.x) {
        int j   = idx >> 7;
        int mat = idx & 127;
        const float2* src = (const float2*)(trans + mat * 16);
        s2[idx] = __ldg(&src[j]);
    }
    __syncthreads();

    // Balanced contiguous group range for this CTA (one CTA per SM).
    const int gStart = (int)((long long)blockIdx.x * G / gridDim.x);
    const int gEnd   = (int)((long long)(blockIdx.x + 1) * G / gridDim.x);
    const int lane   = threadIdx.x & 31;
    const int wid    = threadIdx.x >> 5;
    const int g      = gStart + threadIdx.x;

    const int g0 = gStart + wid * 32;            // warp's first group
    const bool fullWarp = (g0 + 32 <= gEnd) && ((long long)(g0 + 32) * 4 <= N);

    if (fullWarp) {
        // ---- coalesced input load: 3 x 512B LDG.128 per warp -> stage ----
        float4* stage = &sStage[wid * 96];
        const float4* gxyz = xyz4 + (long long)g0 * 3;   // 96 contiguous float4
        stage[ 0 + lane] = __ldg(&gxyz[ 0 + lane]);
        stage[32 + lane] = __ldg(&gxyz[32 + lane]);
        stage[64 + lane] = __ldg(&gxyz[64 + lane]);
        int4 bt = __ldg(&batch4[g]);                     // already coalesced
        __syncwarp();

        float4 a = stage[lane * 3 + 0];
        float4 b = stage[lane * 3 + 1];
        float4 c = stage[lane * 3 + 2];
        __syncwarp();   // stage will be reused for outputs

        float x[4], y[4], z[4];
        x[0] = a.x; y[0] = a.y; z[0] = a.z;
        x[1] = a.w; y[1] = b.x; z[1] = b.y;
        x[2] = b.z; y[2] = b.w; z[2] = c.x;
        x[3] = c.y; y[3] = c.z; z[3] = c.w;

        int b0[4];
        b0[0] = bt.x; b0[1] = bt.y; b0[2] = bt.z; b0[3] = bt.w;
        float fb0[4];
        fb0[0] = (float)bt.x; fb0[1] = (float)bt.y;
        fb0[2] = (float)bt.z; fb0[3] = (float)bt.w;

        const int i0 = g * 4;

        #pragma unroll
        for (int m = 0; m < 8; m++) {
            const int mB = m * BATCH_B;
            const float fmB = (float)mB;
            const long long sliceBase = (long long)m * N;

            float o[12];
            #pragma unroll
            for (int k = 0; k < 4; k++) {
                int nb = b0[k] + mB;
                float2 p0 = s2[0 * NMAT + nb];
                float2 p1 = s2[1 * NMAT + nb];
                float2 p2 = s2[2 * NMAT + nb];
                float2 p3 = s2[3 * NMAT + nb];
                float2 p4 = s2[4 * NMAT + nb];
                float2 p5 = s2[5 * NMAT + nb];
                o[k*3+0] = fmaf(p0.x, x[k], fmaf(p0.y, y[k], fmaf(p1.x, z[k], p1.y)));
                o[k*3+1] = fmaf(p2.x, x[k], fmaf(p2.y, y[k], fmaf(p3.x, z[k], p3.y)));
                o[k*3+2] = fmaf(p4.x, x[k], fmaf(p4.y, y[k], fmaf(p5.x, z[k], p5.y)));
            }

            // Stage: lane l writes chunks 3l..3l+2 (48B) — conflict-free STS.128.
            float4* st = stage + lane * 3;
            st[0] = make_float4(o[0], o[1], o[2],  o[3]);
            st[1] = make_float4(o[4], o[5], o[6],  o[7]);
            st[2] = make_float4(o[8], o[9], o[10], o[11]);
            __syncwarp();

            // Drain: 3 fully contiguous 512B STG.128 (full lines, full sectors).
            float4* gbase = (float4*)(out + (sliceBase + (long long)g0 * 4) * 3);
            #pragma unroll
            for (int j = 0; j < 3; j++) {
                gbase[j * 32 + lane] = stage[j * 32 + lane];
            }
            __syncwarp();   // protect stage reuse next slice

            if (writeBatch) {   // lane-contiguous (16B stride), stays direct
                float4* bo = (float4*)(out + posElems + sliceBase + i0);
                *bo = make_float4(fb0[0] + fmB, fb0[1] + fmB,
                                  fb0[2] + fmB, fb0[3] + fmB);
            }
        }
        return;
    }

    // ---- fallback: partial warp / tail (rare) ----
    if (g >= gEnd) return;
    const int i0 = g * 4;

    if (i0 + 3 < N) {
        float4 a = __ldg(&xyz4[g * 3 + 0]);
        float4 b = __ldg(&xyz4[g * 3 + 1]);
        float4 c = __ldg(&xyz4[g * 3 + 2]);
        int4  bt = __ldg(&batch4[g]);

        float x[4], y[4], z[4];
        x[0] = a.x; y[0] = a.y; z[0] = a.z;
        x[1] = a.w; y[1] = b.x; z[1] = b.y;
        x[2] = b.z; y[2] = b.w; z[2] = c.x;
        x[3] = c.y; y[3] = c.z; z[3] = c.w;

        int b0[4];
        b0[0] = bt.x; b0[1] = bt.y; b0[2] = bt.z; b0[3] = bt.w;
        float fb0[4];
        fb0[0] = (float)bt.x; fb0[1] = (float)bt.y;
        fb0[2] = (float)bt.z; fb0[3] = (float)bt.w;

        for (int m = 0; m < M; m++) {
            int mB = m * BATCH_B;
            float fmB = (float)mB;
            long long sliceBase = (long long)m * N;

            float o[12];
            #pragma unroll
            for (int k = 0; k < 4; k++) {
                int nb = b0[k] + mB;
                float2 p0 = s2[0 * NMAT + nb];
                float2 p1 = s2[1 * NMAT + nb];
                float2 p2 = s2[2 * NMAT + nb];
                float2 p3 = s2[3 * NMAT + nb];
                float2 p4 = s2[4 * NMAT + nb];
                float2 p5 = s2[5 * NMAT + nb];
                o[k*3+0] = fmaf(p0.x, x[k], fmaf(p0.y, y[k], fmaf(p1.x, z[k], p1.y)));
                o[k*3+1] = fmaf(p2.x, x[k], fmaf(p2.y, y[k], fmaf(p3.x, z[k], p3.y)));
                o[k*3+2] = fmaf(p4.x, x[k], fmaf(p4.y, y[k], fmaf(p5.x, z[k], p5.y)));
            }

            float4* outv = (float4*)(out + (sliceBase + i0) * 3);
            outv[0] = make_float4(o[0], o[1], o[2],  o[3]);
            outv[1] = make_float4(o[4], o[5], o[6],  o[7]);
            outv[2] = make_float4(o[8], o[9], o[10], o[11]);

            if (writeBatch) {
                float4* bo = (float4*)(out + posElems + sliceBase + i0);
                *bo = make_float4(fb0[0] + fmB, fb0[1] + fmB,
                                  fb0[2] + fmB, fb0[3] + fmB);
            }
        }
    } else {
        for (int i = i0; i < N; i++) {
            float px = xyz[i * 3 + 0];
            float py = xyz[i * 3 + 1];
            float pz = xyz[i * 3 + 2];
            int bi = __ldg(&batch[i]);
            for (int m = 0; m < M; m++) {
                int nb = bi + m * BATCH_B;
                float2 p0 = s2[0 * NMAT + nb];
                float2 p1 = s2[1 * NMAT + nb];
                float2 p2 = s2[2 * NMAT + nb];
                float2 p3 = s2[3 * NMAT + nb];
                float2 p4 = s2[4 * NMAT + nb];
                float2 p5 = s2[5 * NMAT + nb];
                long long ob = ((long long)m * N + i) * 3;
                out[ob + 0] = fmaf(p0.x, px, fmaf(p0.y, py, fmaf(p1.x, pz, p1.y)));
                out[ob + 1] = fmaf(p2.x, px, fmaf(p2.y, py, fmaf(p3.x, pz, p3.y)));
                out[ob + 2] = fmaf(p4.x, px, fmaf(p4.y, py, fmaf(p5.x, pz, p5.y)));
                if (writeBatch)
                    out[posElems + (long long)m * N + i] = (float)nb;
            }
        }
    }
}

extern "C" void kernel_launch(void* const* d_in, const int* in_sizes, int n_in,
                              void* d_out, int out_size) {
    const float* trans = (const float*)d_in[0];   // [M*B, 4, 4]
    const float* xyz   = (const float*)d_in[1];   // [N, 3]
    const int*   batch = (const int*)d_in[2];     // [N]

    int numMat = in_sizes[0] / 16;        // M*B (= 128)
    int M      = numMat / BATCH_B;        // 8
    int N      = in_sizes[2];             // 500000

    long long posElems = (long long)M * N * 3;
    int writeBatch = ((long long)out_size >= posElems + (long long)M * N) ? 1 : 0;

    int G = (N + 3) / 4;                  // 4-point groups (125000)

    // One fat CTA per SM (mode-W): grid = 152 (GB300), 832 threads = 26 warps.
    int blocks = NSM;
    int threads = THREADS;
    int perCTA = (G + blocks - 1) / blocks;
    if (perCTA > threads) {
        blocks = (G + threads - 1) / threads;
    }

    se3_kernel<<<blocks, threads>>>(
        trans,
        (const float4*)xyz, xyz,
        (const int4*)batch, batch,
        (float*)d_out,
        N, G, M, posElems, writeBatch);
}

// round 17
// speedup vs baseline: 1.0797x; 1.0797x over previous
#include <cuda_runtime.h>
#include <cuda_bf16.h>
#include <cstdint>

// SE3Transform (PARTIAL_DENSE): for m in [0,M), i in [0,N):
//   nb = batch[i] + m*B;  out_pos[m*N+i] = R[nb] @ xyz[i] + p[nb];  out_batch[m*N+i] = nb
// Inputs: trans [M*B,4,4] f32, xyz [N,3] f32, batch [N] i32.
// Output: new_pos.ravel() [M*N*3] f32 ++ new_batch [M*N] as f32.
//
// R13 WIN: staged full-sector stores (21.3->18.2). R15: load staging neutral
// (loads amortized over slices). Ledger: STG.128 issue cost (12cyc x 4/slice
// /warp) is ~1/3 of LSU work.
// R16/R17: drain the staged pos tile via cp.async.bulk shared->global (TMA
// bulk, elected lane) instead of 3 warp-wide STG.128. Batch store stays direct.

#define BATCH_B 16
#define NMAT    128          // M*B
#define NPAIR   6            // float2 pairs per matrix (12 floats)
#define NSM     152          // GB300 SM count
#define THREADS 832
#define WARPS   (THREADS / 32)   // 26

__device__ __forceinline__ uint32_t smem_u32(const void* p) {
    uint32_t a;
    asm("{ .reg .u64 t; cvta.to.shared.u64 t, %1; cvt.u32.u64 %0, t; }"
        : "=r"(a) : "l"(p));
    return a;
}

__global__ void __launch_bounds__(THREADS, 1) se3_kernel(
        const float*  __restrict__ trans,
        const float4* __restrict__ xyz4,
        const float*  __restrict__ xyz,
        const int4*   __restrict__ batch4,
        const int*    __restrict__ batch,
        float* __restrict__ out,
        int N, int G, int M,
        long long posElems, int writeBatch)
{
    // float2-SoA transform table (conflict-free gathers).
    __shared__ float2 s2[NPAIR * NMAT];          // 6 KB
    // Per-warp staging tile: 96 float4 = 1536 B per warp.
    __shared__ float4 sStage[WARPS * 96];        // 39.9 KB

    for (int idx = threadIdx.x; idx < NPAIR * NMAT; idx += blockDim.x) {
        int j   = idx >> 7;
        int mat = idx & 127;
        const float2* src = (const float2*)(trans + mat * 16);
        s2[idx] = __ldg(&src[j]);
    }
    __syncthreads();

    // Balanced contiguous group range for this CTA (one CTA per SM).
    const int gStart = (int)((long long)blockIdx.x * G / gridDim.x);
    const int gEnd   = (int)((long long)(blockIdx.x + 1) * G / gridDim.x);
    const int lane   = threadIdx.x & 31;
    const int wid    = threadIdx.x >> 5;
    const int g      = gStart + threadIdx.x;

    const int g0 = gStart + wid * 32;            // warp's first group
    const bool fullWarp = (g0 + 32 <= gEnd) && ((long long)(g0 + 32) * 4 <= N);

    if (fullWarp) {
        const int i0 = g * 4;
        float4 a = __ldg(&xyz4[g * 3 + 0]);
        float4 b = __ldg(&xyz4[g * 3 + 1]);
        float4 c = __ldg(&xyz4[g * 3 + 2]);
        int4  bt = __ldg(&batch4[g]);

        float x[4], y[4], z[4];
        x[0] = a.x; y[0] = a.y; z[0] = a.z;
        x[1] = a.w; y[1] = b.x; z[1] = b.y;
        x[2] = b.z; y[2] = b.w; z[2] = c.x;
        x[3] = c.y; y[3] = c.z; z[3] = c.w;

        int b0[4];
        b0[0] = bt.x; b0[1] = bt.y; b0[2] = bt.z; b0[3] = bt.w;
        float fb0[4];
        fb0[0] = (float)bt.x; fb0[1] = (float)bt.y;
        fb0[2] = (float)bt.z; fb0[3] = (float)bt.w;

        float4* stage = &sStage[wid * 96];
        const uint32_t stageAddr = smem_u32(stage);

        #pragma unroll
        for (int m = 0; m < 8; m++) {
            const int mB = m * BATCH_B;
            const float fmB = (float)mB;
            const long long sliceBase = (long long)m * N;

            float o[12];
            #pragma unroll
            for (int k = 0; k < 4; k++) {
                int nb = b0[k] + mB;
                float2 p0 = s2[0 * NMAT + nb];
                float2 p1 = s2[1 * NMAT + nb];
                float2 p2 = s2[2 * NMAT + nb];
                float2 p3 = s2[3 * NMAT + nb];
                float2 p4 = s2[4 * NMAT + nb];
                float2 p5 = s2[5 * NMAT + nb];
                o[k*3+0] = fmaf(p0.x, x[k], fmaf(p0.y, y[k], fmaf(p1.x, z[k], p1.y)));
                o[k*3+1] = fmaf(p2.x, x[k], fmaf(p2.y, y[k], fmaf(p3.x, z[k], p3.y)));
                o[k*3+2] = fmaf(p4.x, x[k], fmaf(p4.y, y[k], fmaf(p5.x, z[k], p5.y)));
            }

            // Wait until the previous slice's bulk copy has finished READING
            // the stage (overlapped with the compute above), then refill it.
            if (lane == 0)
                asm volatile("cp.async.bulk.wait_group.read 0;" ::: "memory");
            __syncwarp();

            float4* st = stage + lane * 3;   // conflict-free STS.128
            st[0] = make_float4(o[0], o[1], o[2],  o[3]);
            st[1] = make_float4(o[4], o[5], o[6],  o[7]);
            st[2] = make_float4(o[8], o[9], o[10], o[11]);
            __syncwarp();

            if (lane == 0) {
                asm volatile("fence.proxy.async.shared::cta;" ::: "memory");
                void* gdst = (void*)(out + (sliceBase + (long long)g0 * 4) * 3);
                asm volatile(
                    "cp.async.bulk.global.shared::cta.bulk_group [%0], [%1], %2;"
                    :: "l"(gdst), "r"(stageAddr), "r"(1536) : "memory");
                asm volatile("cp.async.bulk.commit_group;" ::: "memory");
            }

            if (writeBatch) {   // lane-contiguous 16B stride, direct STG.128
                float4* bo = (float4*)(out + posElems + sliceBase + i0);
                *bo = make_float4(fb0[0] + fmB, fb0[1] + fmB,
                                  fb0[2] + fmB, fb0[3] + fmB);
            }
        }

        // Full completion of all bulk stores before kernel exit.
        if (lane == 0)
            asm volatile("cp.async.bulk.wait_group 0;" ::: "memory");
        return;
    }

    // ---- fallback: partial warp / tail (rare) ----
    if (g >= gEnd) return;
    const int i0 = g * 4;

    if (i0 + 3 < N) {
        float4 a = __ldg(&xyz4[g * 3 + 0]);
        float4 b = __ldg(&xyz4[g * 3 + 1]);
        float4 c = __ldg(&xyz4[g * 3 + 2]);
        int4  bt = __ldg(&batch4[g]);

        float x[4], y[4], z[4];
        x[0] = a.x; y[0] = a.y; z[0] = a.z;
        x[1] = a.w; y[1] = b.x; z[1] = b.y;
        x[2] = b.z; y[2] = b.w; z[2] = c.x;
        x[3] = c.y; y[3] = c.z; z[3] = c.w;

        int b0[4];
        b0[0] = bt.x; b0[1] = bt.y; b0[2] = bt.z; b0[3] = bt.w;
        float fb0[4];
        fb0[0] = (float)bt.x; fb0[1] = (float)bt.y;
        fb0[2] = (float)bt.z; fb0[3] = (float)bt.w;

        for (int m = 0; m < M; m++) {
            int mB = m * BATCH_B;
            float fmB = (float)mB;
            long long sliceBase = (long long)m * N;

            float o[12];
            #pragma unroll
            for (int k = 0; k < 4; k++) {
                int nb = b0[k] + mB;
                float2 p0 = s2[0 * NMAT + nb];
                float2 p1 = s2[1 * NMAT + nb];
                float2 p2 = s2[2 * NMAT + nb];
                float2 p3 = s2[3 * NMAT + nb];
                float2 p4 = s2[4 * NMAT + nb];
                float2 p5 = s2[5 * NMAT + nb];
                o[k*3+0] = fmaf(p0.x, x[k], fmaf(p0.y, y[k], fmaf(p1.x, z[k], p1.y)));
                o[k*3+1] = fmaf(p2.x, x[k], fmaf(p2.y, y[k], fmaf(p3.x, z[k], p3.y)));
                o[k*3+2] = fmaf(p4.x, x[k], fmaf(p4.y, y[k], fmaf(p5.x, z[k], p5.y)));
            }

            float4* outv = (float4*)(out + (sliceBase + i0) * 3);
            outv[0] = make_float4(o[0], o[1], o[2],  o[3]);
            outv[1] = make_float4(o[4], o[5], o[6],  o[7]);
            outv[2] = make_float4(o[8], o[9], o[10], o[11]);

            if (writeBatch) {
                float4* bo = (float4*)(out + posElems + sliceBase + i0);
                *bo = make_float4(fb0[0] + fmB, fb0[1] + fmB,
                                  fb0[2] + fmB, fb0[3] + fmB);
            }
        }
    } else {
        for (int i = i0; i < N; i++) {
            float px = xyz[i * 3 + 0];
            float py = xyz[i * 3 + 1];
            float pz = xyz[i * 3 + 2];
            int bi = __ldg(&batch[i]);
            for (int m = 0; m < M; m++) {
                int nb = bi + m * BATCH_B;
                float2 p0 = s2[0 * NMAT + nb];
                float2 p1 = s2[1 * NMAT + nb];
                float2 p2 = s2[2 * NMAT + nb];
                float2 p3 = s2[3 * NMAT + nb];
                float2 p4 = s2[4 * NMAT + nb];
                float2 p5 = s2[5 * NMAT + nb];
                long long ob = ((long long)m * N + i) * 3;
                out[ob + 0] = fmaf(p0.x, px, fmaf(p0.y, py, fmaf(p1.x, pz, p1.y)));
                out[ob + 1] = fmaf(p2.x, px, fmaf(p2.y, py, fmaf(p3.x, pz, p3.y)));
                out[ob + 2] = fmaf(p4.x, px, fmaf(p4.y, py, fmaf(p5.x, pz, p5.y)));
                if (writeBatch)
                    out[posElems + (long long)m * N + i] = (float)nb;
            }
        }
    }
}

extern "C" void kernel_launch(void* const* d_in, const int* in_sizes, int n_in,
                              void* d_out, int out_size) {
    const float* trans = (const float*)d_in[0];   // [M*B, 4, 4]
    const float* xyz   = (const float*)d_in[1];   // [N, 3]
    const int*   batch = (const int*)d_in[2];     // [N]

    int numMat = in_sizes[0] / 16;        // M*B (= 128)
    int M      = numMat / BATCH_B;        // 8
    int N      = in_sizes[2];             // 500000

    long long posElems = (long long)M * N * 3;
    int writeBatch = ((long long)out_size >= posElems + (long long)M * N) ? 1 : 0;

    int G = (N + 3) / 4;                  // 4-point groups (125000)

    // One fat CTA per SM (mode-W): grid = 152 (GB300), 832 threads = 26 warps.
    int blocks = NSM;
    int threads = THREADS;
    int perCTA = (G + blocks - 1) / blocks;
    if (perCTA > threads) {
        blocks = (G + threads - 1) / threads;
    }

    se3_kernel<<<blocks, threads>>>(
        trans,
        (const float4*)xyz, xyz,
        (const int4*)batch, batch,
        (float*)d_out,
        N, G, M, posElems, writeBatch);
}